// round 16
// baseline (speedup 1.0000x reference)
#include <cuda_runtime.h>
#include <cuda_fp16.h>
#include <cstdint>

// ---------------- problem dims ----------------
#define BB   8192
#define HH   1024
#define DIN  1024
#define KXH  2048      // concat [x|h] K
#define NG   4096      // 4 gates * H (Wcat rows interleaved: row 4u+g)
#define DD1  512
#define DD2  341
#define DD2P 384       // padded to multiple of 64 (GK)
#define AA   512

// gates kernel: 128x128 CTA tile, GK=64 k-tiles, 2-stage dynamic smem (2 CTAs/SM)
#define GSTRIDE 72                       // halfs per row (64 data + 8 pad)
#define GSTAGE_BYTES (128 * GSTRIDE * 2) // 18432 per operand per stage
#define G_AB_STAGE (2 * GSTAGE_BYTES)    // 36864
#define G_DSMEM (2 * G_AB_STAGE)         // 73728
#define GNT (KXH / 64)                   // 32 k-tiles (gates)

// decoder GEMM: 64x128 CTA tile, GK=64, 2-stage, 3 CTAs/SM
#define DA_STAGE_BYTES (64 * GSTRIDE * 2)    // 9216
#define DB_STAGE_BYTES (128 * GSTRIDE * 2)   // 18432
#define D_AB_STAGE (DA_STAGE_BYTES + DB_STAGE_BYTES)  // 27648
#define D_DSMEM (2 * D_AB_STAGE)             // 55296

// merged pre-gates prep ranges (threads)
#define RB  HH                           // 1024 bias rows
#define RXV (BB * KXH / 4)               // float4 (XH)
#define RWV (NG * KXH / 4)               // float4 (Wcat)

// merged decoder-weight prep ranges
#define N1V (DD1 * HH / 4)
#define N2V (DD2 * DD1 / 4)
#define N3S (AA * DD2P)

// ---------------- scratch (device globals) ----------------
__device__ __half g_XH[(size_t)BB * KXH];
__device__ __half g_Wcat[(size_t)NG * KXH];    // interleaved rows: 4u+g (g: f,i,s,o)
__device__ float  g_bias[(size_t)HH * 4];      // [u][g] combined b_*i + b_*h
__device__ __half g_hnew[(size_t)BB * HH];
__device__ __half g_Wd1[(size_t)DD1 * HH];
__device__ __half g_d1[(size_t)BB * DD1];
__device__ __half g_Wd2[(size_t)DD2 * DD1];
__device__ __half g_d2[(size_t)BB * DD2P];     // cols 341..383 zero
__device__ __half g_Wd3[(size_t)AA * DD2P];    // cols 341..383 zero
__device__ float  g_logits[(size_t)BB * AA];

// ---------------- helpers ----------------
__device__ __forceinline__ void cp_async16(void* smem, const void* gmem, int bytes) {
    uint32_t s = (uint32_t)__cvta_generic_to_shared(smem);
    asm volatile("cp.async.ca.shared.global [%0], [%1], 16, %2;\n"
                 :: "r"(s), "l"(gmem), "r"(bytes));
}
__device__ __forceinline__ void cp_commit() {
    asm volatile("cp.async.commit_group;\n" ::: "memory");
}
__device__ __forceinline__ void ldsm4(uint32_t& r0, uint32_t& r1, uint32_t& r2, uint32_t& r3,
                                      const void* p) {
    uint32_t a = (uint32_t)__cvta_generic_to_shared(p);
    asm volatile("ldmatrix.sync.aligned.m8n8.x4.shared.b16 {%0,%1,%2,%3}, [%4];"
                 : "=r"(r0), "=r"(r1), "=r"(r2), "=r"(r3) : "r"(a));
}
__device__ __forceinline__ void mma16816(float* c, const uint32_t* a, const uint32_t* b) {
    asm volatile("mma.sync.aligned.m16n8k16.row.col.f32.f16.f16.f32 "
                 "{%0,%1,%2,%3}, {%4,%5,%6,%7}, {%8,%9}, {%0,%1,%2,%3};"
                 : "+f"(c[0]), "+f"(c[1]), "+f"(c[2]), "+f"(c[3])
                 : "r"(a[0]), "r"(a[1]), "r"(a[2]), "r"(a[3]), "r"(b[0]), "r"(b[1]));
}
__device__ __forceinline__ float sigmoidf_(float x) { return 1.0f / (1.0f + __expf(-x)); }

// ---------------- merged pre-gates prep: bias + XH + Wcat ----------------
__global__ void k_prep_all(const float* __restrict__ x, const float* __restrict__ h,
                           const float* __restrict__ bfi, const float* __restrict__ bfh,
                           const float* __restrict__ bii, const float* __restrict__ bih,
                           const float* __restrict__ bsi, const float* __restrict__ bsh,
                           const float* __restrict__ boi, const float* __restrict__ boh,
                           const float* __restrict__ Wfi, const float* __restrict__ Wfh,
                           const float* __restrict__ Wii, const float* __restrict__ Wih,
                           const float* __restrict__ Wsi, const float* __restrict__ Wsh,
                           const float* __restrict__ Woi, const float* __restrict__ Woh) {
    int i = blockIdx.x * blockDim.x + threadIdx.x;
    if (i < RB) {
        int u = i;
        float4 v = make_float4(bfi[u] + bfh[u], bii[u] + bih[u],
                               bsi[u] + bsh[u], boi[u] + boh[u]);
        *reinterpret_cast<float4*>(g_bias + u * 4) = v;
    } else if (i < RB + RXV) {
        int i4 = (i - RB) * 4;
        int b = i4 >> 11, k = i4 & 2047;
        const float* src = (k < DIN) ? (x + (size_t)b * DIN + k)
                                     : (h + (size_t)b * HH + (k - DIN));
        float4 v = *reinterpret_cast<const float4*>(src);
        __half2* dst = reinterpret_cast<__half2*>(g_XH + i4);
        dst[0] = __floats2half2_rn(v.x, v.y);
        dst[1] = __floats2half2_rn(v.z, v.w);
    } else {
        int j = i - RB - RXV;
        if (j >= RWV) return;
        int i4 = j * 4;
        int n = i4 >> 11, k = i4 & 2047;
        int u = n >> 2, g = n & 3;
        bool second = (k >= 1024);
        int kk = second ? (k - 1024) : k;
        const float* base;
        switch (g) {
            case 0:  base = second ? Wfh : Wfi; break;
            case 1:  base = second ? Wih : Wii; break;
            case 2:  base = second ? Wsh : Wsi; break;
            default: base = second ? Woh : Woi; break;
        }
        float4 v = *reinterpret_cast<const float4*>(base + (size_t)u * 1024 + kk);
        __half2* dst = reinterpret_cast<__half2*>(g_Wcat + i4);
        dst[0] = __floats2half2_rn(v.x, v.y);
        dst[1] = __floats2half2_rn(v.z, v.w);
    }
}

// merged decoder-weight prep: W_d1 + W_d2 (flat vec4) + W_d3 (pad 341->384)
__global__ void k_prep_dec(const float* __restrict__ W1, const float* __restrict__ W2,
                           const float* __restrict__ W3) {
    int i = blockIdx.x * blockDim.x + threadIdx.x;
    if (i < N1V) {
        int i4 = i * 4;
        float4 v = *reinterpret_cast<const float4*>(W1 + i4);
        __half2* d = reinterpret_cast<__half2*>(g_Wd1 + i4);
        d[0] = __floats2half2_rn(v.x, v.y);
        d[1] = __floats2half2_rn(v.z, v.w);
    } else if (i < N1V + N2V) {
        int i4 = (i - N1V) * 4;
        float4 v = *reinterpret_cast<const float4*>(W2 + i4);
        __half2* d = reinterpret_cast<__half2*>(g_Wd2 + i4);
        d[0] = __floats2half2_rn(v.x, v.y);
        d[1] = __floats2half2_rn(v.z, v.w);
    } else {
        int j = i - N1V - N2V;
        if (j < N3S) {
            int r = j / DD2P, c = j % DD2P;
            g_Wd3[j] = __float2half((c < DD2) ? W3[(size_t)r * DD2 + c] : 0.0f);
        }
    }
}

// ---------------- gates: HMMA 128x128, GK=64, 2-stage, 2 CTAs/SM + fused LSTM (R12) ------------
__global__ __launch_bounds__(256, 2)
void k_gates_fused(const float* __restrict__ cin, float* __restrict__ out) {
    extern __shared__ __align__(16) char dsm[];

    const int bm = blockIdx.y * 128;
    const int bn = blockIdx.x * 128;
    const int tid = threadIdx.x;
    const int lane = tid & 31;
    const int wid = tid >> 5;
    const int wm = (wid & 3) * 32;
    const int wn = (wid >> 2) * 64;

    float acc[2][8][4];
#pragma unroll
    for (int mi = 0; mi < 2; mi++)
#pragma unroll
        for (int nj = 0; nj < 8; nj++)
#pragma unroll
            for (int q = 0; q < 4; q++) acc[mi][nj][q] = 0.0f;

    const int lr0 = tid >> 3;
    const int lc = (tid & 7) * 8;

    auto Sa = [&](int st) { return reinterpret_cast<__half*>(dsm + st * G_AB_STAGE); };
    auto Sb = [&](int st) { return reinterpret_cast<__half*>(dsm + st * G_AB_STAGE + GSTAGE_BYTES); };

    auto load_tile = [&](int st, int kt) {
        int k0 = kt * 64;
        __half* As = Sa(st);
        __half* Bs = Sb(st);
#pragma unroll
        for (int i = 0; i < 4; i++) {
            int row = lr0 + i * 32;
            cp_async16(As + row * GSTRIDE + lc, g_XH + (size_t)(bm + row) * KXH + k0 + lc, 16);
        }
#pragma unroll
        for (int i = 0; i < 4; i++) {
            int row = lr0 + i * 32;
            cp_async16(Bs + row * GSTRIDE + lc, g_Wcat + (size_t)(bn + row) * KXH + k0 + lc, 16);
        }
    };

    auto compute = [&](int st) {
        const __half* As = Sa(st);
        const __half* Bs = Sb(st);
#pragma unroll
        for (int ks = 0; ks < 4; ks++) {
            int k0 = ks * 16;
            uint32_t af[2][4];
#pragma unroll
            for (int mi = 0; mi < 2; mi++) {
                int arow = wm + mi * 16 + (lane & 15);
                int acol = k0 + (lane >> 4) * 8;
                ldsm4(af[mi][0], af[mi][1], af[mi][2], af[mi][3], As + arow * GSTRIDE + acol);
            }
            uint32_t bfr[8][2];
#pragma unroll
            for (int nj = 0; nj < 4; nj++) {
                int nrow = wn + nj * 16 + (lane & 7) + ((lane >> 4) << 3);
                int kcol = k0 + ((lane >> 3) & 1) * 8;
                uint32_t r0, r1, r2, r3;
                ldsm4(r0, r1, r2, r3, Bs + nrow * GSTRIDE + kcol);
                bfr[2 * nj][0] = r0; bfr[2 * nj][1] = r1;
                bfr[2 * nj + 1][0] = r2; bfr[2 * nj + 1][1] = r3;
            }
#pragma unroll
            for (int mi = 0; mi < 2; mi++)
#pragma unroll
                for (int nj = 0; nj < 8; nj++)
                    mma16816(acc[mi][nj], af[mi], bfr[nj]);
        }
    };

    load_tile(0, 0);
    cp_commit();
    int buf = 0;
    for (int kt = 0; kt < GNT; kt++) {
        asm volatile("cp.async.wait_group 0;\n" ::: "memory");
        __syncthreads();
        if (kt + 1 < GNT) {
            load_tile(buf ^ 1, kt + 1);
            cp_commit();
        }
        compute(buf);
        buf ^= 1;
    }

    // ---- fused LSTM epilogue ----
    __syncthreads();
    float* cs = reinterpret_cast<float*>(dsm);
    float* stage = cs + 128 * 33;
    const int ubase = bn >> 2;

#pragma unroll
    for (int i = 0; i < 4; i++) {
        int idx = tid + i * 256;
        int row = idx >> 3, c4 = (idx & 7) * 4;
        float4 v = *reinterpret_cast<const float4*>(cin + (size_t)(bm + row) * HH + ubase + c4);
        cs[row * 33 + c4 + 0] = v.x;
        cs[row * 33 + c4 + 1] = v.y;
        cs[row * 33 + c4 + 2] = v.z;
        cs[row * 33 + c4 + 3] = v.w;
    }
    __syncthreads();

    const int groupr = lane >> 2;
    const int quad = lane & 3;
    const bool evenq = (quad & 1) == 0;
    const int rsel = (quad & 1) * 8;
    const int lrow0 = wm + groupr + rsel;

#pragma unroll
    for (int mi = 0; mi < 2; mi++) {
        int lrow = lrow0 + mi * 16;
#pragma unroll
        for (int nj = 0; nj < 8; nj++) {
            int lu = ((wn + nj * 8) >> 2) + (quad >> 1);
            int u = ubase + lu;
            float o0 = __shfl_xor_sync(0xffffffffu, acc[mi][nj][0], 1);
            float o1 = __shfl_xor_sync(0xffffffffu, acc[mi][nj][1], 1);
            float o2 = __shfl_xor_sync(0xffffffffu, acc[mi][nj][2], 1);
            float o3 = __shfl_xor_sync(0xffffffffu, acc[mi][nj][3], 1);
            float zf = evenq ? acc[mi][nj][0] : o2;
            float zi = evenq ? acc[mi][nj][1] : o3;
            float zs = evenq ? o0 : acc[mi][nj][2];
            float zo = evenq ? o1 : acc[mi][nj][3];
            float4 gb = *reinterpret_cast<const float4*>(g_bias + (size_t)u * 4);
            float f  = sigmoidf_(zf + gb.x);
            float ii = sigmoidf_(zi + gb.y);
            float s  = tanhf(zs + gb.z);
            float og = sigmoidf_(zo + gb.w);
            float cn = cs[lrow * 33 + lu] * f + ii * s;
            stage[lrow * 33 + lu] = og * tanhf(cn);
        }
    }
    __syncthreads();

#pragma unroll
    for (int i = 0; i < 4; i++) {
        int idx = tid + i * 256;
        int row = idx >> 3, c4 = (idx & 7) * 4;
        float v0 = stage[row * 33 + c4 + 0];
        float v1 = stage[row * 33 + c4 + 1];
        float v2 = stage[row * 33 + c4 + 2];
        float v3 = stage[row * 33 + c4 + 3];
        *reinterpret_cast<float4*>(out + (size_t)(bm + row) * HH + ubase + c4) =
            make_float4(v0, v1, v2, v3);
        __half2* hp = reinterpret_cast<__half2*>(g_hnew + (size_t)(bm + row) * HH + ubase + c4);
        hp[0] = __floats2half2_rn(v0, v1);
        hp[1] = __floats2half2_rn(v2, v3);
    }
}

// ---------------- decoder GEMM: 64x128 CTA tile, GK=64, 2-stage, 3 CTAs/SM ----------------
// 256 threads, 8 warps: warp tile 16x64, wm=(wid&3)*16, wn=(wid>>2)*64.
template <int ACT, bool HASBIAS, bool OUTF32>
__global__ __launch_bounds__(256, 3)
void gemm_fp16(const __half* __restrict__ Aop, int lda,
               const __half* __restrict__ Bop, int ldb, int Brows,
               const float* __restrict__ bias,
               float* __restrict__ outF, __half* __restrict__ outB, int ldc,
               int Nstore, int Nvalid, int K) {
    extern __shared__ __align__(16) char dsm[];

    const int bm = blockIdx.y * 64;
    const int bn = blockIdx.x * 128;
    const int tid = threadIdx.x;
    const int lane = tid & 31;
    const int wid = tid >> 5;
    const int wm = (wid & 3) * 16;
    const int wn = (wid >> 2) * 64;

    float acc[8][4];
#pragma unroll
    for (int nj = 0; nj < 8; nj++)
#pragma unroll
        for (int q = 0; q < 4; q++) acc[nj][q] = 0.0f;

    const int lr0 = tid >> 3;          // 0..31
    const int lc = (tid & 7) * 8;

    auto Sa = [&](int st) { return reinterpret_cast<__half*>(dsm + st * D_AB_STAGE); };
    auto Sb = [&](int st) { return reinterpret_cast<__half*>(dsm + st * D_AB_STAGE + DA_STAGE_BYTES); };

    auto load_tile = [&](int st, int kt) {
        int k0 = kt * 64;
        __half* As = Sa(st);
        __half* Bs = Sb(st);
#pragma unroll
        for (int i = 0; i < 2; i++) {
            int row = lr0 + i * 32;       // 0..63
            cp_async16(As + row * GSTRIDE + lc, Aop + (size_t)(bm + row) * lda + k0 + lc, 16);
        }
#pragma unroll
        for (int i = 0; i < 4; i++) {
            int row = lr0 + i * 32;       // 0..127
            int gn = bn + row;
            bool ok = gn < Brows;
            const __half* srcB = Bop + (size_t)(ok ? gn : 0) * ldb + k0 + lc;
            cp_async16(Bs + row * GSTRIDE + lc, srcB, ok ? 16 : 0);
        }
    };

    auto compute = [&](int st) {
        const __half* As = Sa(st);
        const __half* Bs = Sb(st);
#pragma unroll
        for (int ks = 0; ks < 4; ks++) {
            int k0 = ks * 16;
            uint32_t af[4];
            {
                int arow = wm + (lane & 15);
                int acol = k0 + (lane >> 4) * 8;
                ldsm4(af[0], af[1], af[2], af[3], As + arow * GSTRIDE + acol);
            }
            uint32_t bfr[8][2];
#pragma unroll
            for (int nj = 0; nj < 4; nj++) {
                int nrow = wn + nj * 16 + (lane & 7) + ((lane >> 4) << 3);
                int kcol = k0 + ((lane >> 3) & 1) * 8;
                uint32_t r0, r1, r2, r3;
                ldsm4(r0, r1, r2, r3, Bs + nrow * GSTRIDE + kcol);
                bfr[2 * nj][0] = r0; bfr[2 * nj][1] = r1;
                bfr[2 * nj + 1][0] = r2; bfr[2 * nj + 1][1] = r3;
            }
#pragma unroll
            for (int nj = 0; nj < 8; nj++)
                mma16816(acc[nj], af, bfr[nj]);
        }
    };

    const int NTl = K / 64;
    load_tile(0, 0);
    cp_commit();
    int buf = 0;
    for (int kt = 0; kt < NTl; kt++) {
        asm volatile("cp.async.wait_group 0;\n" ::: "memory");
        __syncthreads();
        if (kt + 1 < NTl) {
            load_tile(buf ^ 1, kt + 1);
            cp_commit();
        }
        compute(buf);
        buf ^= 1;
    }

    const int groupr = lane >> 2;
    const int cc = (lane & 3) * 2;
#pragma unroll
    for (int nj = 0; nj < 8; nj++) {
        int col = bn + wn + nj * 8 + cc;
        if (col >= Nstore) continue;
        float b0 = 0.0f, b1 = 0.0f;
        if (HASBIAS) {
            b0 = (col < Nvalid) ? bias[col] : 0.0f;
            b1 = (col + 1 < Nvalid) ? bias[col + 1] : 0.0f;
        }
#pragma unroll
        for (int rr = 0; rr < 2; rr++) {
            int row = bm + wm + groupr + rr * 8;
            float v0 = acc[nj][rr * 2 + 0] + b0;
            float v1 = acc[nj][rr * 2 + 1] + b1;
            if (ACT == 1) { v0 = tanhf(v0); v1 = tanhf(v1); }
            if (col >= Nvalid) v0 = 0.0f;
            if (col + 1 >= Nvalid) v1 = 0.0f;
            if (OUTF32) {
                float2* p = reinterpret_cast<float2*>(outF + (size_t)row * ldc + col);
                *p = make_float2(v0, v1);
            } else {
                __half2* p = reinterpret_cast<__half2*>(outB + (size_t)row * ldc + col);
                *p = __floats2half2_rn(v0, v1);
            }
        }
    }
}

// ---------------- softmax ----------------
__global__ void k_softmax(float* __restrict__ out) {
    int row = blockIdx.x * 8 + (threadIdx.x >> 5);
    int lane = threadIdx.x & 31;
    const float* Lr = g_logits + (size_t)row * AA;
    float vals[16];
    float mx = -1e30f;
#pragma unroll
    for (int j = 0; j < 16; j++) {
        vals[j] = Lr[lane + j * 32];
        mx = fmaxf(mx, vals[j]);
    }
#pragma unroll
    for (int off = 16; off > 0; off >>= 1)
        mx = fmaxf(mx, __shfl_xor_sync(0xffffffffu, mx, off));
    float s = 0.0f;
#pragma unroll
    for (int j = 0; j < 16; j++) {
        vals[j] = __expf(vals[j] - mx);
        s += vals[j];
    }
#pragma unroll
    for (int off = 16; off > 0; off >>= 1)
        s += __shfl_xor_sync(0xffffffffu, s, off);
    float inv = 1.0f / s;
    float* orow = out + (size_t)BB * HH + (size_t)row * AA;
#pragma unroll
    for (int j = 0; j < 16; j++) orow[lane + j * 32] = vals[j] * inv;
}

// ---------------- launch ----------------
extern "C" void kernel_launch(void* const* d_in, const int* in_sizes, int n_in,
                              void* d_out, int out_size) {
    const float* x    = (const float*)d_in[0];
    const float* h    = (const float*)d_in[1];
    const float* c    = (const float*)d_in[2];
    const float* W_fi = (const float*)d_in[3];
    const float* b_fi = (const float*)d_in[4];
    const float* W_fh = (const float*)d_in[5];
    const float* b_fh = (const float*)d_in[6];
    const float* W_ii = (const float*)d_in[7];
    const float* b_ii = (const float*)d_in[8];
    const float* W_ih = (const float*)d_in[9];
    const float* b_ih = (const float*)d_in[10];
    const float* W_si = (const float*)d_in[11];
    const float* b_si = (const float*)d_in[12];
    const float* W_sh = (const float*)d_in[13];
    const float* b_sh = (const float*)d_in[14];
    const float* W_oi = (const float*)d_in[15];
    const float* b_oi = (const float*)d_in[16];
    const float* W_oh = (const float*)d_in[17];
    const float* b_oh = (const float*)d_in[18];
    const float* W_d1 = (const float*)d_in[19];
    const float* b_d1 = (const float*)d_in[20];
    const float* W_d2 = (const float*)d_in[21];
    const float* b_d2 = (const float*)d_in[22];
    const float* W_d3 = (const float*)d_in[23];
    const float* b_d3 = (const float*)d_in[24];
    float* out = (float*)d_out;

    __half *hnew, *Wd1, *d1, *Wd2, *d2, *Wd3;
    float* logits;
    cudaGetSymbolAddress((void**)&hnew, g_hnew);
    cudaGetSymbolAddress((void**)&Wd1, g_Wd1);
    cudaGetSymbolAddress((void**)&d1, g_d1);
    cudaGetSymbolAddress((void**)&Wd2, g_Wd2);
    cudaGetSymbolAddress((void**)&d2, g_d2);
    cudaGetSymbolAddress((void**)&Wd3, g_Wd3);
    cudaGetSymbolAddress((void**)&logits, g_logits);

    cudaFuncSetAttribute(k_gates_fused, cudaFuncAttributeMaxDynamicSharedMemorySize, G_DSMEM);
    cudaFuncSetAttribute(gemm_fp16<1, true, false>,
                         cudaFuncAttributeMaxDynamicSharedMemorySize, D_DSMEM);
    cudaFuncSetAttribute(gemm_fp16<0, true, true>,
                         cudaFuncAttributeMaxDynamicSharedMemorySize, D_DSMEM);

    // #1: merged pre-gates prep; #2: gates; #3: decoder prep; #4: decoder gemm1 (ncu target)
    k_prep_all<<<(RB + RXV + RWV + 255) / 256, 256>>>(
        x, h, b_fi, b_fh, b_ii, b_ih, b_si, b_sh, b_oi, b_oh,
        W_fi, W_fh, W_ii, W_ih, W_si, W_sh, W_oi, W_oh);

    k_gates_fused<<<dim3(NG / 128, BB / 128), 256, G_DSMEM>>>(c, out);

    k_prep_dec<<<(N1V + N2V + N3S + 255) / 256, 256>>>(W_d1, W_d2, W_d3);

    // decoder (HMMA fp16, 64x128 tiles, 3 CTAs/SM)
    gemm_fp16<1, true, false><<<dim3(DD1 / 128, BB / 64), 256, D_DSMEM>>>(
        hnew, HH, Wd1, HH, DD1, b_d1, nullptr, d1, DD1, DD1, DD1, HH);
    gemm_fp16<1, true, false><<<dim3(DD2P / 128, BB / 64), 256, D_DSMEM>>>(
        d1, DD1, Wd2, DD1, DD2, b_d2, nullptr, d2, DD2P, DD2P, DD2, DD1);
    gemm_fp16<0, true, true><<<dim3(AA / 128, BB / 64), 256, D_DSMEM>>>(
        d2, DD2P, Wd3, DD2P, AA, b_d3, logits, nullptr, AA, AA, AA, DD2P);

    // softmax -> out[B*H:]
    k_softmax<<<BB / 8, 256>>>(out);
}

// round 17
// speedup vs baseline: 1.0254x; 1.0254x over previous
#include <cuda_runtime.h>
#include <cuda_fp16.h>
#include <cstdint>

// ---------------- problem dims ----------------
#define BB   8192
#define HH   1024
#define DIN  1024
#define KXH  2048      // concat [x|h] K
#define NG   4096      // 4 gates * H (Wcat rows interleaved: row 4u+g)
#define DD1  512
#define DD2  341
#define DD2P 384       // padded to multiple of 64 (GK)
#define AA   512

// GEMM kernels: 128x128 CTA tile, GK=64 k-tiles, 2-stage dynamic smem (2 CTAs/SM)
#define GSTRIDE 72                       // halfs per row (64 data + 8 pad)
#define GSTAGE_BYTES (128 * GSTRIDE * 2) // 18432 per operand per stage
#define G_AB_STAGE (2 * GSTAGE_BYTES)    // 36864
#define G_DSMEM (2 * G_AB_STAGE)         // 73728
#define GNT (KXH / 64)                   // 32 k-tiles (gates)

// merged prep ranges (threads)
#define RB  HH                           // 1024 bias rows
#define RXV (BB * KXH / 4)               // float4 (XH)
#define RWV (NG * KXH / 4)               // float4 (Wcat)
#define N1V (DD1 * HH / 4)               // float4 (W_d1)
#define N2V (DD2 * DD1 / 4)              // float4 (W_d2)
#define N3S (AA * DD2P)                  // scalar (W_d3 pad)
#define RTOT (RB + RXV + RWV + N1V + N2V + N3S)

// ---------------- scratch (device globals) ----------------
__device__ __half g_XH[(size_t)BB * KXH];
__device__ __half g_Wcat[(size_t)NG * KXH];    // interleaved rows: 4u+g (g: f,i,s,o)
__device__ float  g_bias[(size_t)HH * 4];      // [u][g] combined b_*i + b_*h
__device__ __half g_hnew[(size_t)BB * HH];
__device__ __half g_Wd1[(size_t)DD1 * HH];
__device__ __half g_d1[(size_t)BB * DD1];
__device__ __half g_Wd2[(size_t)DD2 * DD1];
__device__ __half g_d2[(size_t)BB * DD2P];     // cols 341..383 zero
__device__ __half g_Wd3[(size_t)AA * DD2P];    // cols 341..383 zero
__device__ float  g_logits[(size_t)BB * AA];

// ---------------- helpers ----------------
__device__ __forceinline__ void cp_async16(void* smem, const void* gmem, int bytes) {
    uint32_t s = (uint32_t)__cvta_generic_to_shared(smem);
    asm volatile("cp.async.ca.shared.global [%0], [%1], 16, %2;\n"
                 :: "r"(s), "l"(gmem), "r"(bytes));
}
__device__ __forceinline__ void cp_commit() {
    asm volatile("cp.async.commit_group;\n" ::: "memory");
}
__device__ __forceinline__ void ldsm4(uint32_t& r0, uint32_t& r1, uint32_t& r2, uint32_t& r3,
                                      const void* p) {
    uint32_t a = (uint32_t)__cvta_generic_to_shared(p);
    asm volatile("ldmatrix.sync.aligned.m8n8.x4.shared.b16 {%0,%1,%2,%3}, [%4];"
                 : "=r"(r0), "=r"(r1), "=r"(r2), "=r"(r3) : "r"(a));
}
__device__ __forceinline__ void mma16816(float* c, const uint32_t* a, const uint32_t* b) {
    asm volatile("mma.sync.aligned.m16n8k16.row.col.f32.f16.f16.f32 "
                 "{%0,%1,%2,%3}, {%4,%5,%6,%7}, {%8,%9}, {%0,%1,%2,%3};"
                 : "+f"(c[0]), "+f"(c[1]), "+f"(c[2]), "+f"(c[3])
                 : "r"(a[0]), "r"(a[1]), "r"(a[2]), "r"(a[3]), "r"(b[0]), "r"(b[1]));
}
__device__ __forceinline__ float sigmoidf_(float x) { return 1.0f / (1.0f + __expf(-x)); }

// ---------------- merged prep: bias + XH + Wcat + Wd1 + Wd2 + Wd3 ----------------
__global__ void k_prep_all(const float* __restrict__ x, const float* __restrict__ h,
                           const float* __restrict__ bfi, const float* __restrict__ bfh,
                           const float* __restrict__ bii, const float* __restrict__ bih,
                           const float* __restrict__ bsi, const float* __restrict__ bsh,
                           const float* __restrict__ boi, const float* __restrict__ boh,
                           const float* __restrict__ Wfi, const float* __restrict__ Wfh,
                           const float* __restrict__ Wii, const float* __restrict__ Wih,
                           const float* __restrict__ Wsi, const float* __restrict__ Wsh,
                           const float* __restrict__ Woi, const float* __restrict__ Woh,
                           const float* __restrict__ W1, const float* __restrict__ W2,
                           const float* __restrict__ W3) {
    int i = blockIdx.x * blockDim.x + threadIdx.x;
    if (i < RB) {
        int u = i;
        float4 v = make_float4(bfi[u] + bfh[u], bii[u] + bih[u],
                               bsi[u] + bsh[u], boi[u] + boh[u]);
        *reinterpret_cast<float4*>(g_bias + u * 4) = v;
    } else if (i < RB + RXV) {
        int i4 = (i - RB) * 4;
        int b = i4 >> 11, k = i4 & 2047;
        const float* src = (k < DIN) ? (x + (size_t)b * DIN + k)
                                     : (h + (size_t)b * HH + (k - DIN));
        float4 v = *reinterpret_cast<const float4*>(src);
        __half2* dst = reinterpret_cast<__half2*>(g_XH + i4);
        dst[0] = __floats2half2_rn(v.x, v.y);
        dst[1] = __floats2half2_rn(v.z, v.w);
    } else if (i < RB + RXV + RWV) {
        int i4 = (i - RB - RXV) * 4;
        int n = i4 >> 11, k = i4 & 2047;
        int u = n >> 2, g = n & 3;
        bool second = (k >= 1024);
        int kk = second ? (k - 1024) : k;
        const float* base;
        switch (g) {
            case 0:  base = second ? Wfh : Wfi; break;
            case 1:  base = second ? Wih : Wii; break;
            case 2:  base = second ? Wsh : Wsi; break;
            default: base = second ? Woh : Woi; break;
        }
        float4 v = *reinterpret_cast<const float4*>(base + (size_t)u * 1024 + kk);
        __half2* dst = reinterpret_cast<__half2*>(g_Wcat + i4);
        dst[0] = __floats2half2_rn(v.x, v.y);
        dst[1] = __floats2half2_rn(v.z, v.w);
    } else if (i < RB + RXV + RWV + N1V) {
        int i4 = (i - RB - RXV - RWV) * 4;
        float4 v = *reinterpret_cast<const float4*>(W1 + i4);
        __half2* d = reinterpret_cast<__half2*>(g_Wd1 + i4);
        d[0] = __floats2half2_rn(v.x, v.y);
        d[1] = __floats2half2_rn(v.z, v.w);
    } else if (i < RB + RXV + RWV + N1V + N2V) {
        int i4 = (i - RB - RXV - RWV - N1V) * 4;
        float4 v = *reinterpret_cast<const float4*>(W2 + i4);
        __half2* d = reinterpret_cast<__half2*>(g_Wd2 + i4);
        d[0] = __floats2half2_rn(v.x, v.y);
        d[1] = __floats2half2_rn(v.z, v.w);
    } else {
        int j = i - RB - RXV - RWV - N1V - N2V;
        if (j < N3S) {
            int r = j / DD2P, c = j % DD2P;
            g_Wd3[j] = __float2half((c < DD2) ? W3[(size_t)r * DD2 + c] : 0.0f);
        }
    }
}

// ---------------- gates: HMMA 128x128, GK=64, 2-stage, 2 CTAs/SM + fused LSTM (R12) ------------
__global__ __launch_bounds__(256, 2)
void k_gates_fused(const float* __restrict__ cin, float* __restrict__ out) {
    extern __shared__ __align__(16) char dsm[];

    const int bm = blockIdx.y * 128;
    const int bn = blockIdx.x * 128;
    const int tid = threadIdx.x;
    const int lane = tid & 31;
    const int wid = tid >> 5;
    const int wm = (wid & 3) * 32;
    const int wn = (wid >> 2) * 64;

    float acc[2][8][4];
#pragma unroll
    for (int mi = 0; mi < 2; mi++)
#pragma unroll
        for (int nj = 0; nj < 8; nj++)
#pragma unroll
            for (int q = 0; q < 4; q++) acc[mi][nj][q] = 0.0f;

    const int lr0 = tid >> 3;
    const int lc = (tid & 7) * 8;

    auto Sa = [&](int st) { return reinterpret_cast<__half*>(dsm + st * G_AB_STAGE); };
    auto Sb = [&](int st) { return reinterpret_cast<__half*>(dsm + st * G_AB_STAGE + GSTAGE_BYTES); };

    auto load_tile = [&](int st, int kt) {
        int k0 = kt * 64;
        __half* As = Sa(st);
        __half* Bs = Sb(st);
#pragma unroll
        for (int i = 0; i < 4; i++) {
            int row = lr0 + i * 32;
            cp_async16(As + row * GSTRIDE + lc, g_XH + (size_t)(bm + row) * KXH + k0 + lc, 16);
        }
#pragma unroll
        for (int i = 0; i < 4; i++) {
            int row = lr0 + i * 32;
            cp_async16(Bs + row * GSTRIDE + lc, g_Wcat + (size_t)(bn + row) * KXH + k0 + lc, 16);
        }
    };

    auto compute = [&](int st) {
        const __half* As = Sa(st);
        const __half* Bs = Sb(st);
#pragma unroll
        for (int ks = 0; ks < 4; ks++) {
            int k0 = ks * 16;
            uint32_t af[2][4];
#pragma unroll
            for (int mi = 0; mi < 2; mi++) {
                int arow = wm + mi * 16 + (lane & 15);
                int acol = k0 + (lane >> 4) * 8;
                ldsm4(af[mi][0], af[mi][1], af[mi][2], af[mi][3], As + arow * GSTRIDE + acol);
            }
            uint32_t bfr[8][2];
#pragma unroll
            for (int nj = 0; nj < 4; nj++) {
                int nrow = wn + nj * 16 + (lane & 7) + ((lane >> 4) << 3);
                int kcol = k0 + ((lane >> 3) & 1) * 8;
                uint32_t r0, r1, r2, r3;
                ldsm4(r0, r1, r2, r3, Bs + nrow * GSTRIDE + kcol);
                bfr[2 * nj][0] = r0; bfr[2 * nj][1] = r1;
                bfr[2 * nj + 1][0] = r2; bfr[2 * nj + 1][1] = r3;
            }
#pragma unroll
            for (int mi = 0; mi < 2; mi++)
#pragma unroll
                for (int nj = 0; nj < 8; nj++)
                    mma16816(acc[mi][nj], af[mi], bfr[nj]);
        }
    };

    load_tile(0, 0);
    cp_commit();
    int buf = 0;
    for (int kt = 0; kt < GNT; kt++) {
        asm volatile("cp.async.wait_group 0;\n" ::: "memory");
        __syncthreads();
        if (kt + 1 < GNT) {
            load_tile(buf ^ 1, kt + 1);
            cp_commit();
        }
        compute(buf);
        buf ^= 1;
    }

    // ---- fused LSTM epilogue ----
    __syncthreads();
    float* cs = reinterpret_cast<float*>(dsm);
    float* stage = cs + 128 * 33;
    const int ubase = bn >> 2;

#pragma unroll
    for (int i = 0; i < 4; i++) {
        int idx = tid + i * 256;
        int row = idx >> 3, c4 = (idx & 7) * 4;
        float4 v = *reinterpret_cast<const float4*>(cin + (size_t)(bm + row) * HH + ubase + c4);
        cs[row * 33 + c4 + 0] = v.x;
        cs[row * 33 + c4 + 1] = v.y;
        cs[row * 33 + c4 + 2] = v.z;
        cs[row * 33 + c4 + 3] = v.w;
    }
    __syncthreads();

    const int groupr = lane >> 2;
    const int quad = lane & 3;
    const bool evenq = (quad & 1) == 0;
    const int rsel = (quad & 1) * 8;
    const int lrow0 = wm + groupr + rsel;

#pragma unroll
    for (int mi = 0; mi < 2; mi++) {
        int lrow = lrow0 + mi * 16;
#pragma unroll
        for (int nj = 0; nj < 8; nj++) {
            int lu = ((wn + nj * 8) >> 2) + (quad >> 1);
            int u = ubase + lu;
            float o0 = __shfl_xor_sync(0xffffffffu, acc[mi][nj][0], 1);
            float o1 = __shfl_xor_sync(0xffffffffu, acc[mi][nj][1], 1);
            float o2 = __shfl_xor_sync(0xffffffffu, acc[mi][nj][2], 1);
            float o3 = __shfl_xor_sync(0xffffffffu, acc[mi][nj][3], 1);
            float zf = evenq ? acc[mi][nj][0] : o2;
            float zi = evenq ? acc[mi][nj][1] : o3;
            float zs = evenq ? o0 : acc[mi][nj][2];
            float zo = evenq ? o1 : acc[mi][nj][3];
            float4 gb = *reinterpret_cast<const float4*>(g_bias + (size_t)u * 4);
            float f  = sigmoidf_(zf + gb.x);
            float ii = sigmoidf_(zi + gb.y);
            float s  = tanhf(zs + gb.z);
            float og = sigmoidf_(zo + gb.w);
            float cn = cs[lrow * 33 + lu] * f + ii * s;
            stage[lrow * 33 + lu] = og * tanhf(cn);
        }
    }
    __syncthreads();

#pragma unroll
    for (int i = 0; i < 4; i++) {
        int idx = tid + i * 256;
        int row = idx >> 3, c4 = (idx & 7) * 4;
        float v0 = stage[row * 33 + c4 + 0];
        float v1 = stage[row * 33 + c4 + 1];
        float v2 = stage[row * 33 + c4 + 2];
        float v3 = stage[row * 33 + c4 + 3];
        *reinterpret_cast<float4*>(out + (size_t)(bm + row) * HH + ubase + c4) =
            make_float4(v0, v1, v2, v3);
        __half2* hp = reinterpret_cast<__half2*>(g_hnew + (size_t)(bm + row) * HH + ubase + c4);
        hp[0] = __floats2half2_rn(v0, v1);
        hp[1] = __floats2half2_rn(v2, v3);
    }
}

// ---------------- HMMA GEMM (decoder layers): 128x128, GK=64, 2-stage, 2 CTAs/SM (R15) --------
template <int ACT, bool HASBIAS, bool OUTF32>
__global__ __launch_bounds__(256, 2)
void gemm_fp16(const __half* __restrict__ Aop, int lda,
               const __half* __restrict__ Bop, int ldb, int Brows,
               const float* __restrict__ bias,
               float* __restrict__ outF, __half* __restrict__ outB, int ldc,
               int Nstore, int Nvalid, int K) {
    extern __shared__ __align__(16) char dsm[];

    const int bm = blockIdx.y * 128;
    const int bn = blockIdx.x * 128;
    const int tid = threadIdx.x;
    const int lane = tid & 31;
    const int wid = tid >> 5;
    const int wm = (wid & 3) * 32;
    const int wn = (wid >> 2) * 64;

    float acc[2][8][4];
#pragma unroll
    for (int mi = 0; mi < 2; mi++)
#pragma unroll
        for (int nj = 0; nj < 8; nj++)
#pragma unroll
            for (int q = 0; q < 4; q++) acc[mi][nj][q] = 0.0f;

    const int lr0 = tid >> 3;
    const int lc = (tid & 7) * 8;

    auto Sa = [&](int st) { return reinterpret_cast<__half*>(dsm + st * G_AB_STAGE); };
    auto Sb = [&](int st) { return reinterpret_cast<__half*>(dsm + st * G_AB_STAGE + GSTAGE_BYTES); };

    auto load_tile = [&](int st, int kt) {
        int k0 = kt * 64;
        __half* As = Sa(st);
        __half* Bs = Sb(st);
#pragma unroll
        for (int i = 0; i < 4; i++) {
            int row = lr0 + i * 32;
            cp_async16(As + row * GSTRIDE + lc, Aop + (size_t)(bm + row) * lda + k0 + lc, 16);
        }
#pragma unroll
        for (int i = 0; i < 4; i++) {
            int row = lr0 + i * 32;
            int gn = bn + row;
            bool ok = gn < Brows;
            const __half* srcB = Bop + (size_t)(ok ? gn : 0) * ldb + k0 + lc;
            cp_async16(Bs + row * GSTRIDE + lc, srcB, ok ? 16 : 0);
        }
    };

    auto compute = [&](int st) {
        const __half* As = Sa(st);
        const __half* Bs = Sb(st);
#pragma unroll
        for (int ks = 0; ks < 4; ks++) {
            int k0 = ks * 16;
            uint32_t af[2][4];
#pragma unroll
            for (int mi = 0; mi < 2; mi++) {
                int arow = wm + mi * 16 + (lane & 15);
                int acol = k0 + (lane >> 4) * 8;
                ldsm4(af[mi][0], af[mi][1], af[mi][2], af[mi][3], As + arow * GSTRIDE + acol);
            }
            uint32_t bfr[8][2];
#pragma unroll
            for (int nj = 0; nj < 4; nj++) {
                int nrow = wn + nj * 16 + (lane & 7) + ((lane >> 4) << 3);
                int kcol = k0 + ((lane >> 3) & 1) * 8;
                uint32_t r0, r1, r2, r3;
                ldsm4(r0, r1, r2, r3, Bs + nrow * GSTRIDE + kcol);
                bfr[2 * nj][0] = r0; bfr[2 * nj][1] = r1;
                bfr[2 * nj + 1][0] = r2; bfr[2 * nj + 1][1] = r3;
            }
#pragma unroll
            for (int mi = 0; mi < 2; mi++)
#pragma unroll
                for (int nj = 0; nj < 8; nj++)
                    mma16816(acc[mi][nj], af[mi], bfr[nj]);
        }
    };

    const int NTl = K / 64;
    load_tile(0, 0);
    cp_commit();
    int buf = 0;
    for (int kt = 0; kt < NTl; kt++) {
        asm volatile("cp.async.wait_group 0;\n" ::: "memory");
        __syncthreads();
        if (kt + 1 < NTl) {
            load_tile(buf ^ 1, kt + 1);
            cp_commit();
        }
        compute(buf);
        buf ^= 1;
    }

    const int groupr = lane >> 2;
    const int cc = (lane & 3) * 2;
#pragma unroll
    for (int mi = 0; mi < 2; mi++) {
#pragma unroll
        for (int nj = 0; nj < 8; nj++) {
            int col = bn + wn + nj * 8 + cc;
            if (col >= Nstore) continue;
            float b0 = 0.0f, b1 = 0.0f;
            if (HASBIAS) {
                b0 = (col < Nvalid) ? bias[col] : 0.0f;
                b1 = (col + 1 < Nvalid) ? bias[col + 1] : 0.0f;
            }
#pragma unroll
            for (int rr = 0; rr < 2; rr++) {
                int row = bm + wm + mi * 16 + groupr + rr * 8;
                float v0 = acc[mi][nj][rr * 2 + 0] + b0;
                float v1 = acc[mi][nj][rr * 2 + 1] + b1;
                if (ACT == 1) { v0 = tanhf(v0); v1 = tanhf(v1); }
                if (col >= Nvalid) v0 = 0.0f;
                if (col + 1 >= Nvalid) v1 = 0.0f;
                if (OUTF32) {
                    float2* p = reinterpret_cast<float2*>(outF + (size_t)row * ldc + col);
                    *p = make_float2(v0, v1);
                } else {
                    __half2* p = reinterpret_cast<__half2*>(outB + (size_t)row * ldc + col);
                    *p = __floats2half2_rn(v0, v1);
                }
            }
        }
    }
}

// ---------------- softmax ----------------
__global__ void k_softmax(float* __restrict__ out) {
    int row = blockIdx.x * 8 + (threadIdx.x >> 5);
    int lane = threadIdx.x & 31;
    const float* Lr = g_logits + (size_t)row * AA;
    float vals[16];
    float mx = -1e30f;
#pragma unroll
    for (int j = 0; j < 16; j++) {
        vals[j] = Lr[lane + j * 32];
        mx = fmaxf(mx, vals[j]);
    }
#pragma unroll
    for (int off = 16; off > 0; off >>= 1)
        mx = fmaxf(mx, __shfl_xor_sync(0xffffffffu, mx, off));
    float s = 0.0f;
#pragma unroll
    for (int j = 0; j < 16; j++) {
        vals[j] = __expf(vals[j] - mx);
        s += vals[j];
    }
#pragma unroll
    for (int off = 16; off > 0; off >>= 1)
        s += __shfl_xor_sync(0xffffffffu, s, off);
    float inv = 1.0f / s;
    float* orow = out + (size_t)BB * HH + (size_t)row * AA;
#pragma unroll
    for (int j = 0; j < 16; j++) orow[lane + j * 32] = vals[j] * inv;
}

// ---------------- launch ----------------
extern "C" void kernel_launch(void* const* d_in, const int* in_sizes, int n_in,
                              void* d_out, int out_size) {
    const float* x    = (const float*)d_in[0];
    const float* h    = (const float*)d_in[1];
    const float* c    = (const float*)d_in[2];
    const float* W_fi = (const float*)d_in[3];
    const float* b_fi = (const float*)d_in[4];
    const float* W_fh = (const float*)d_in[5];
    const float* b_fh = (const float*)d_in[6];
    const float* W_ii = (const float*)d_in[7];
    const float* b_ii = (const float*)d_in[8];
    const float* W_ih = (const float*)d_in[9];
    const float* b_ih = (const float*)d_in[10];
    const float* W_si = (const float*)d_in[11];
    const float* b_si = (const float*)d_in[12];
    const float* W_sh = (const float*)d_in[13];
    const float* b_sh = (const float*)d_in[14];
    const float* W_oi = (const float*)d_in[15];
    const float* b_oi = (const float*)d_in[16];
    const float* W_oh = (const float*)d_in[17];
    const float* b_oh = (const float*)d_in[18];
    const float* W_d1 = (const float*)d_in[19];
    const float* b_d1 = (const float*)d_in[20];
    const float* W_d2 = (const float*)d_in[21];
    const float* b_d2 = (const float*)d_in[22];
    const float* W_d3 = (const float*)d_in[23];
    const float* b_d3 = (const float*)d_in[24];
    float* out = (float*)d_out;

    __half *hnew, *Wd1, *d1, *Wd2, *d2, *Wd3;
    float* logits;
    cudaGetSymbolAddress((void**)&hnew, g_hnew);
    cudaGetSymbolAddress((void**)&Wd1, g_Wd1);
    cudaGetSymbolAddress((void**)&d1, g_d1);
    cudaGetSymbolAddress((void**)&Wd2, g_Wd2);
    cudaGetSymbolAddress((void**)&d2, g_d2);
    cudaGetSymbolAddress((void**)&Wd3, g_Wd3);
    cudaGetSymbolAddress((void**)&logits, g_logits);

    cudaFuncSetAttribute(k_gates_fused, cudaFuncAttributeMaxDynamicSharedMemorySize, G_DSMEM);
    cudaFuncSetAttribute(gemm_fp16<1, true, false>,
                         cudaFuncAttributeMaxDynamicSharedMemorySize, G_DSMEM);
    cudaFuncSetAttribute(gemm_fp16<0, true, true>,
                         cudaFuncAttributeMaxDynamicSharedMemorySize, G_DSMEM);

    // #1: merged prep (all); #2: gates; #3-5: decoder; #6: softmax
    k_prep_all<<<(RTOT + 255) / 256, 256>>>(
        x, h, b_fi, b_fh, b_ii, b_ih, b_si, b_sh, b_oi, b_oh,
        W_fi, W_fh, W_ii, W_ih, W_si, W_sh, W_oi, W_oh,
        W_d1, W_d2, W_d3);

    k_gates_fused<<<dim3(NG / 128, BB / 128), 256, G_DSMEM>>>(c, out);

    // decoder (HMMA fp16, 128x128 tiles, 2 CTAs/SM)
    gemm_fp16<1, true, false><<<dim3(DD1 / 128, BB / 128), 256, G_DSMEM>>>(
        hnew, HH, Wd1, HH, DD1, b_d1, nullptr, d1, DD1, DD1, DD1, HH);
    gemm_fp16<1, true, false><<<dim3(DD2P / 128, BB / 128), 256, G_DSMEM>>>(
        d1, DD1, Wd2, DD1, DD2, b_d2, nullptr, d2, DD2P, DD2P, DD2, DD1);
    gemm_fp16<0, true, true><<<dim3(AA / 128, BB / 128), 256, G_DSMEM>>>(
        d2, DD2P, Wd3, DD2P, AA, b_d3, logits, nullptr, AA, AA, AA, DD2P);

    // softmax -> out[B*H:]
    k_softmax<<<BB / 8, 256>>>(out);
}